// round 6
// baseline (speedup 1.0000x reference)
#include <cuda_runtime.h>

#define NUM_SP 1024
#define NPIX   (512 * 512)
#define NFEAT  256
#define NCLS   21
#define PAD    8   // segment start alignment in g_sorted (for int4 index loads)

// Scratch: __device__ globals (zero-initialized at load; segment_kernel restores
// the zeroed state at the end of every call -> deterministic across calls)
__device__ int g_flag;               // 0 => labels int64 (odd words all zero), 1 => int32
__device__ int g_counts[NUM_SP];
__device__ int g_offsets[NUM_SP];    // padded exclusive offsets (multiples of 8)
__device__ int g_cursor[NUM_SP];
__device__ __align__(16) int g_sorted[NPIX + PAD * NUM_SP];

// ---------------- Pass 0: dtype probe (reads only NPIX int32 words -> in-bounds
// for both int32 and int64 label buffers) ----------------
__global__ void probe_kernel(const int* __restrict__ sp32) {
    int i = blockIdx.x * blockDim.x + threadIdx.x;      // 0 .. NPIX/2-1
    int2 p = ((const int2*)sp32)[i];                    // coalesced, words [0, NPIX)
    unsigned any = __ballot_sync(0xffffffffu, p.y != 0);
    if ((threadIdx.x & 31) == 0 && any) atomicOr(&g_flag, 1);
}

__device__ __forceinline__ int load_label(const int* __restrict__ sp32, int i) {
    int idx = (g_flag == 0) ? (i << 1) : i;             // int64 -> low word at 2*i
    int s = sp32[idx];
    return min(max(s, 0), NUM_SP - 1);
}

// ---------------- Pass 1: histogram (g_counts zeroed by previous call's cleanup) --
__global__ void hist_kernel(const int* __restrict__ sp32) {
    int i = blockIdx.x * blockDim.x + threadIdx.x;
    if (i < NPIX) {
        int s = load_label(sp32, i);
        atomicAdd(&g_counts[s], 1);
    }
}

// ---------------- Pass 2: exclusive scan of 8-padded counts (warp shuffles) ------
__global__ void scan_kernel() {
    __shared__ int warp_sums[32];
    int t = threadIdx.x;
    int lane = t & 31, wid = t >> 5;
    int c  = g_counts[t];
    int cp = (c + PAD - 1) & ~(PAD - 1);
    int x = cp;
    #pragma unroll
    for (int off = 1; off < 32; off <<= 1) {
        int v = __shfl_up_sync(0xffffffffu, x, off);
        if (lane >= off) x += v;
    }
    if (lane == 31) warp_sums[wid] = x;
    __syncthreads();
    if (t < 32) {
        int s = warp_sums[t];
        #pragma unroll
        for (int off = 1; off < 32; off <<= 1) {
            int v = __shfl_up_sync(0xffffffffu, s, off);
            if (t >= off) s += v;
        }
        warp_sums[t] = s;    // inclusive warp totals
    }
    __syncthreads();
    int base = (wid > 0) ? warp_sums[wid - 1] : 0;
    int excl = base + x - cp;
    g_offsets[t] = excl;
    g_cursor[t]  = excl;
}

// ---------------- Pass 3: scatter pixel indices, sorted by label -----------------
__global__ void scatter_kernel(const int* __restrict__ sp32) {
    int i = blockIdx.x * blockDim.x + threadIdx.x;
    if (i < NPIX) {
        int s = load_label(sp32, i);
        int pos = atomicAdd(&g_cursor[s], 1);
        g_sorted[pos] = i;
    }
}

// ---------------- Pass 4: per-segment gather-sum + projection --------------------
// One CTA per segment, 256 threads = 4 groups x 64 float4 lanes. Each group takes
// a CONTIGUOUS 8-aligned run of pixels; per iteration: 2 int4 index loads + 8
// independent __ldcs float4 loads (MLP~8), 2 accumulator chains.
__global__ void __launch_bounds__(256) segment_kernel(
    const float* __restrict__ feat,
    const float* __restrict__ w,     // (21, 256) row-major
    float* __restrict__ out)         // (1024, 21)
{
    const int b   = blockIdx.x;
    const int tid = threadIdx.x;
    const int l   = tid & 63;
    const int g   = tid >> 6;

    const int start = g_offsets[b];                    // multiple of 8
    const int cnt   = g_counts[b];
    const int per   = ((cnt + 31) >> 5) << 3;          // ceil(cnt/4) rounded up to 8
    const int lo    = g * per;
    const int hi    = min(lo + per, cnt);

    const float4* __restrict__ f4 = (const float4*)feat;

    float4 a0 = make_float4(0.f, 0.f, 0.f, 0.f);
    float4 a1 = make_float4(0.f, 0.f, 0.f, 0.f);

    int p = lo;
    for (; p + 8 <= hi; p += 8) {
        const int4 ia = *(const int4*)(g_sorted + start + p);      // 16B aligned
        const int4 ib = *(const int4*)(g_sorted + start + p + 4);
        float4 v0 = __ldcs(&f4[(size_t)ia.x * 64 + l]);
        float4 v1 = __ldcs(&f4[(size_t)ia.y * 64 + l]);
        float4 v2 = __ldcs(&f4[(size_t)ia.z * 64 + l]);
        float4 v3 = __ldcs(&f4[(size_t)ia.w * 64 + l]);
        float4 v4 = __ldcs(&f4[(size_t)ib.x * 64 + l]);
        float4 v5 = __ldcs(&f4[(size_t)ib.y * 64 + l]);
        float4 v6 = __ldcs(&f4[(size_t)ib.z * 64 + l]);
        float4 v7 = __ldcs(&f4[(size_t)ib.w * 64 + l]);
        a0.x += v0.x; a0.y += v0.y; a0.z += v0.z; a0.w += v0.w;
        a1.x += v1.x; a1.y += v1.y; a1.z += v1.z; a1.w += v1.w;
        a0.x += v2.x; a0.y += v2.y; a0.z += v2.z; a0.w += v2.w;
        a1.x += v3.x; a1.y += v3.y; a1.z += v3.z; a1.w += v3.w;
        a0.x += v4.x; a0.y += v4.y; a0.z += v4.z; a0.w += v4.w;
        a1.x += v5.x; a1.y += v5.y; a1.z += v5.z; a1.w += v5.w;
        a0.x += v6.x; a0.y += v6.y; a0.z += v6.z; a0.w += v6.w;
        a1.x += v7.x; a1.y += v7.y; a1.z += v7.z; a1.w += v7.w;
    }
    for (; p < hi; ++p) {
        int i0 = g_sorted[start + p];
        float4 v = __ldcs(&f4[(size_t)i0 * 64 + l]);
        a0.x += v.x; a0.y += v.y; a0.z += v.z; a0.w += v.w;
    }
    float4 acc = make_float4(a0.x + a1.x, a0.y + a1.y, a0.z + a1.z, a0.w + a1.w);

    // Cross-group reduce in shared memory
    __shared__ float s_part[4][NFEAT];
    __shared__ float s_nf[NFEAT];
    ((float4*)s_part[g])[l] = acc;
    __syncthreads();

    const float inv = 1.0f / (float)max(cnt, 1);
    float nf = (s_part[0][tid] + s_part[1][tid] + s_part[2][tid] + s_part[3][tid]) * inv;
    s_nf[tid] = nf;
    __syncthreads();

    // Projection: 21 dot products; warp wid handles classes wid, wid+8, wid+16
    const int wid  = tid >> 5;
    const int lane = tid & 31;
    for (int c = wid; c < NCLS; c += 8) {
        const float* __restrict__ wr = w + c * NFEAT;
        float part = 0.f;
        #pragma unroll
        for (int j = 0; j < 8; j++) {
            int f = lane + 32 * j;
            part += s_nf[f] * __ldg(&wr[f]);
        }
        #pragma unroll
        for (int o = 16; o > 0; o >>= 1)
            part += __shfl_down_sync(0xffffffffu, part, o);
        if (lane == 0)
            out[b * NCLS + c] = part;
    }

    // ---- cleanup for next call: restore zeroed-global invariant ----
    if (tid == 0) {
        g_counts[b] = 0;
        if (b == 0) g_flag = 0;
    }
}

extern "C" void kernel_launch(void* const* d_in, const int* in_sizes, int n_in,
                              void* d_out, int out_size) {
    const float* feat = (const float*)d_in[0];   // (1,512,512,256) f32
    const int*   sp32 = (const int*)d_in[1];     // (512,512) int32 or int64 (probed)
    const float* w    = (const float*)d_in[2];   // (21,256) f32
    float* out = (float*)d_out;                  // (1024,21) f32

    probe_kernel<<<NPIX / 2 / 256, 256>>>(sp32);
    hist_kernel<<<NPIX / 256, 256>>>(sp32);
    scan_kernel<<<1, NUM_SP>>>();
    scatter_kernel<<<NPIX / 256, 256>>>(sp32);
    segment_kernel<<<NUM_SP, 256>>>(feat, w, out);
}

// round 8
// speedup vs baseline: 1.3972x; 1.3972x over previous
#include <cuda_runtime.h>

#define NUM_SP  1024
#define NPIX    (512 * 512)
#define NFEAT   256
#define NCLS    21
#define PAD     8
#define NBLK    64          // pixel blocks for the counting sort
#define PPB     (NPIX / NBLK)   // 4096 pixels per block

// Scratch (__device__ globals; every array fully rewritten each call, g_flag
// restored by segment_kernel -> deterministic across graph replays)
__device__ int g_flag;                       // 0 => labels int64, 1 => int32
__device__ int g_counts[NUM_SP];
__device__ int g_offsets[NUM_SP];            // 8-padded exclusive offsets
__device__ int g_blockhist[NBLK * NUM_SP];   // [blk][label]
__device__ int g_blockbase[NBLK * NUM_SP];   // [blk][label] -> global start
__device__ __align__(16) int g_sorted[NPIX + PAD * NUM_SP];

// ---------------- Pass 0: dtype probe (reads NPIX int32 words; in-bounds for
// both int32 and int64 label buffers) ----------------
__global__ void probe_kernel(const int* __restrict__ sp32) {
    int i = blockIdx.x * blockDim.x + threadIdx.x;      // 0 .. NPIX/2-1
    int2 p = ((const int2*)sp32)[i];
    unsigned any = __ballot_sync(0xffffffffu, p.y != 0);
    if ((threadIdx.x & 31) == 0 && any) atomicOr(&g_flag, 1);
}

__device__ __forceinline__ int load_label(const int* __restrict__ sp32, int i) {
    int idx = (g_flag == 0) ? (i << 1) : i;             // int64 -> low word at 2*i
    int s = sp32[idx];
    return min(max(s, 0), NUM_SP - 1);
}

// ---------------- Pass A: per-block histogram (smem atomics only) ----------------
__global__ void __launch_bounds__(1024) hist_block_kernel(const int* __restrict__ sp32) {
    __shared__ int h[NUM_SP];
    const int c = blockIdx.x, t = threadIdx.x;
    h[t] = 0;
    __syncthreads();
    #pragma unroll
    for (int k = 0; k < PPB / 1024; k++) {
        int i = c * PPB + k * 1024 + t;
        atomicAdd(&h[load_label(sp32, i)], 1);
    }
    __syncthreads();
    g_blockhist[c * NUM_SP + t] = h[t];
}

// ---------------- Pass B: totals + padded scan + per-block bases -----------------
__global__ void __launch_bounds__(1024) scan_kernel() {
    __shared__ int warp_sums[32];
    const int t = threadIdx.x, lane = t & 31, wid = t >> 5;

    // total count per label (coalesced column sum, MLP 8)
    int cnt = 0;
    #pragma unroll
    for (int c0 = 0; c0 < NBLK; c0 += 8) {
        int v0 = g_blockhist[(c0 + 0) * NUM_SP + t];
        int v1 = g_blockhist[(c0 + 1) * NUM_SP + t];
        int v2 = g_blockhist[(c0 + 2) * NUM_SP + t];
        int v3 = g_blockhist[(c0 + 3) * NUM_SP + t];
        int v4 = g_blockhist[(c0 + 4) * NUM_SP + t];
        int v5 = g_blockhist[(c0 + 5) * NUM_SP + t];
        int v6 = g_blockhist[(c0 + 6) * NUM_SP + t];
        int v7 = g_blockhist[(c0 + 7) * NUM_SP + t];
        cnt += v0 + v1 + v2 + v3 + v4 + v5 + v6 + v7;
    }
    g_counts[t] = cnt;

    // CTA-wide exclusive scan of 8-padded counts
    int cp = (cnt + PAD - 1) & ~(PAD - 1);
    int x = cp;
    #pragma unroll
    for (int off = 1; off < 32; off <<= 1) {
        int v = __shfl_up_sync(0xffffffffu, x, off);
        if (lane >= off) x += v;
    }
    if (lane == 31) warp_sums[wid] = x;
    __syncthreads();
    if (t < 32) {
        int s = warp_sums[t];
        #pragma unroll
        for (int off = 1; off < 32; off <<= 1) {
            int v = __shfl_up_sync(0xffffffffu, s, off);
            if (t >= off) s += v;
        }
        warp_sums[t] = s;
    }
    __syncthreads();
    int excl = ((wid > 0) ? warp_sums[wid - 1] : 0) + x - cp;
    g_offsets[t] = excl;

    // per-(block,label) bases: running prefix down the column (MLP 8 per batch)
    int running = excl;
    #pragma unroll
    for (int c0 = 0; c0 < NBLK; c0 += 8) {
        int v[8];
        #pragma unroll
        for (int j = 0; j < 8; j++) v[j] = g_blockhist[(c0 + j) * NUM_SP + t];
        #pragma unroll
        for (int j = 0; j < 8; j++) {
            g_blockbase[(c0 + j) * NUM_SP + t] = running;
            running += v[j];
        }
    }
}

// ---------------- Pass C: scatter (smem rank atomics only, no global atomics) ----
__global__ void __launch_bounds__(1024) scatter_block_kernel(const int* __restrict__ sp32) {
    __shared__ int sbase[NUM_SP];
    __shared__ int rank[NUM_SP];
    const int c = blockIdx.x, t = threadIdx.x;
    sbase[t] = g_blockbase[c * NUM_SP + t];
    rank[t]  = 0;
    __syncthreads();
    #pragma unroll
    for (int k = 0; k < PPB / 1024; k++) {
        int i = c * PPB + k * 1024 + t;
        int s = load_label(sp32, i);
        int r = atomicAdd(&rank[s], 1);
        g_sorted[sbase[s] + r] = i;
    }
}

// ---------------- Pass 4: per-segment gather-sum + projection --------------------
// One CTA per segment. 256 threads = 4 pixel-groups x 64 float4 lanes.
__global__ void __launch_bounds__(256) segment_kernel(
    const float* __restrict__ feat,
    const float* __restrict__ w,     // (21, 256) row-major
    float* __restrict__ out)         // (1024, 21)
{
    const int b   = blockIdx.x;
    const int tid = threadIdx.x;
    const int l   = tid & 63;
    const int g   = tid >> 6;

    const int start = g_offsets[b];
    const int cnt   = g_counts[b];

    const float4* __restrict__ f4 = (const float4*)feat;

    float4 acc = make_float4(0.f, 0.f, 0.f, 0.f);

    int p = g;
    for (; p + 12 < cnt; p += 16) {
        int i0 = g_sorted[start + p];
        int i1 = g_sorted[start + p + 4];
        int i2 = g_sorted[start + p + 8];
        int i3 = g_sorted[start + p + 12];
        float4 v0 = __ldcs(&f4[(size_t)i0 * 64 + l]);
        float4 v1 = __ldcs(&f4[(size_t)i1 * 64 + l]);
        float4 v2 = __ldcs(&f4[(size_t)i2 * 64 + l]);
        float4 v3 = __ldcs(&f4[(size_t)i3 * 64 + l]);
        acc.x += v0.x; acc.y += v0.y; acc.z += v0.z; acc.w += v0.w;
        acc.x += v1.x; acc.y += v1.y; acc.z += v1.z; acc.w += v1.w;
        acc.x += v2.x; acc.y += v2.y; acc.z += v2.z; acc.w += v2.w;
        acc.x += v3.x; acc.y += v3.y; acc.z += v3.z; acc.w += v3.w;
    }
    for (; p < cnt; p += 4) {
        int i0 = g_sorted[start + p];
        float4 v = __ldcs(&f4[(size_t)i0 * 64 + l]);
        acc.x += v.x; acc.y += v.y; acc.z += v.z; acc.w += v.w;
    }

    __shared__ float s_part[4][NFEAT];
    __shared__ float s_nf[NFEAT];
    ((float4*)s_part[g])[l] = acc;
    __syncthreads();

    const float inv = 1.0f / (float)max(cnt, 1);
    float nf = (s_part[0][tid] + s_part[1][tid] + s_part[2][tid] + s_part[3][tid]) * inv;
    s_nf[tid] = nf;
    __syncthreads();

    const int wid  = tid >> 5;
    const int lane = tid & 31;
    for (int c = wid; c < NCLS; c += 8) {
        const float* __restrict__ wr = w + c * NFEAT;
        float part = 0.f;
        #pragma unroll
        for (int j = 0; j < 8; j++) {
            int f = lane + 32 * j;
            part += s_nf[f] * __ldg(&wr[f]);
        }
        #pragma unroll
        for (int o = 16; o > 0; o >>= 1)
            part += __shfl_down_sync(0xffffffffu, part, o);
        if (lane == 0)
            out[b * NCLS + c] = part;
    }

    // restore zeroed-global invariant for the next call
    if (tid == 0 && b == 0) g_flag = 0;
}

extern "C" void kernel_launch(void* const* d_in, const int* in_sizes, int n_in,
                              void* d_out, int out_size) {
    const float* feat = (const float*)d_in[0];   // (1,512,512,256) f32
    const int*   sp32 = (const int*)d_in[1];     // (512,512) int32 or int64 (probed)
    const float* w    = (const float*)d_in[2];   // (21,256) f32
    float* out = (float*)d_out;                  // (1024,21) f32

    probe_kernel<<<NPIX / 2 / 256, 256>>>(sp32);
    hist_block_kernel<<<NBLK, 1024>>>(sp32);
    scan_kernel<<<1, 1024>>>();
    scatter_block_kernel<<<NBLK, 1024>>>(sp32);
    segment_kernel<<<NUM_SP, 256>>>(feat, w, out);
}